// round 1
// baseline (speedup 1.0000x reference)
#include <cuda_runtime.h>
#include <cstdio>

#define D_MODEL 1024
#define N_HEADS 16
#define HEAD    64
#define BATCH   2
#define SEQ     2048
#define M_TOT   (BATCH * SEQ)

// Scratch for projected Q/K/V (16 MB each) — __device__ globals per harness rules.
__device__ float g_qp[M_TOT * D_MODEL];
__device__ float g_kp[M_TOT * D_MODEL];
__device__ float g_vp[M_TOT * D_MODEL];

// ---------------------------------------------------------------------------
// Projection GEMM: Y[m][n] = sum_k X[m][k] * W[n][k] + bias[n]
// M=4096, N=1024, K=1024. 128x128 block, 8x8 per thread, BK=8.
// ---------------------------------------------------------------------------
__global__ __launch_bounds__(256) void proj_gemm(
    const float* __restrict__ X, const float* __restrict__ W,
    const float* __restrict__ bias, float* __restrict__ Y)
{
    __shared__ float As[8][128];
    __shared__ float Bs[8][128];

    const int tid  = threadIdx.x;
    const int bm   = blockIdx.y * 128;
    const int bn   = blockIdx.x * 128;
    const int lrow = tid >> 1;          // 0..127
    const int lcol = (tid & 1) << 2;    // 0 or 4
    const int ty   = tid >> 4;          // 0..15
    const int tx   = tid & 15;          // 0..15

    const float* Aptr = X + (size_t)(bm + lrow) * 1024 + lcol;
    const float* Bptr = W + (size_t)(bn + lrow) * 1024 + lcol;

    float acc[8][8];
#pragma unroll
    for (int i = 0; i < 8; i++)
#pragma unroll
        for (int j = 0; j < 8; j++) acc[i][j] = 0.0f;

    for (int k0 = 0; k0 < 1024; k0 += 8) {
        float4 a = *(const float4*)(Aptr + k0);
        float4 b = *(const float4*)(Bptr + k0);
        As[lcol + 0][lrow] = a.x; As[lcol + 1][lrow] = a.y;
        As[lcol + 2][lrow] = a.z; As[lcol + 3][lrow] = a.w;
        Bs[lcol + 0][lrow] = b.x; Bs[lcol + 1][lrow] = b.y;
        Bs[lcol + 2][lrow] = b.z; Bs[lcol + 3][lrow] = b.w;
        __syncthreads();

#pragma unroll
        for (int k = 0; k < 8; k++) {
            float ra[8], rb[8];
            *(float4*)&ra[0] = *(const float4*)&As[k][ty * 4];
            *(float4*)&ra[4] = *(const float4*)&As[k][64 + ty * 4];
            *(float4*)&rb[0] = *(const float4*)&Bs[k][tx * 4];
            *(float4*)&rb[4] = *(const float4*)&Bs[k][64 + tx * 4];
#pragma unroll
            for (int i = 0; i < 8; i++)
#pragma unroll
                for (int j = 0; j < 8; j++)
                    acc[i][j] += ra[i] * rb[j];
        }
        __syncthreads();
    }

    const float4 b0 = *(const float4*)(bias + bn + tx * 4);
    const float4 b1 = *(const float4*)(bias + bn + 64 + tx * 4);
#pragma unroll
    for (int i = 0; i < 8; i++) {
        int row = bm + ((i < 4) ? (ty * 4 + i) : (64 + ty * 4 + (i - 4)));
        float4 r0 = make_float4(acc[i][0] + b0.x, acc[i][1] + b0.y,
                                acc[i][2] + b0.z, acc[i][3] + b0.w);
        float4 r1 = make_float4(acc[i][4] + b1.x, acc[i][5] + b1.y,
                                acc[i][6] + b1.z, acc[i][7] + b1.w);
        *(float4*)(Y + (size_t)row * 1024 + bn + tx * 4) = r0;
        *(float4*)(Y + (size_t)row * 1024 + bn + 64 + tx * 4) = r1;
    }
}

// ---------------------------------------------------------------------------
// Flash-style attention, fp32. One block per (q-tile of 64, head, batch).
// 256 threads = 16x16; each thread owns 4 q-rows x 4 cols.
// Online softmax; P staged through smem for the PV GEMM.
// ---------------------------------------------------------------------------
#define QS_STRIDE 68   // padded row stride (floats) for Qs/Ks; 68*4 bytes, 16B-aligned

__global__ __launch_bounds__(256) void attn_kernel(
    const float* __restrict__ QP, const float* __restrict__ KP,
    const float* __restrict__ VP, const float* __restrict__ mask,
    float* __restrict__ out)
{
    extern __shared__ float sm[];
    float* Qs = sm;                       // [64][68]
    float* Ks = Qs + 64 * QS_STRIDE;      // [64][68]
    float* Vs = Ks + 64 * QS_STRIDE;      // [64][64]
    float* Ps = Vs + 64 * 64;             // [64][64]

    const int tid = threadIdx.x;
    const int ty  = tid >> 4;   // 0..15 -> q rows ty*4..+3
    const int tx  = tid & 15;   // 0..15 -> cols tx*4..+3
    const int q0  = blockIdx.x * 64;
    const int h   = blockIdx.y;
    const int b   = blockIdx.z;

    const size_t base = (size_t)b * SEQ * D_MODEL + (size_t)h * HEAD;

    // Load Q tile, pre-scaled by 1/sqrt(HEAD) = 0.125
    for (int i = tid; i < 64 * 16; i += 256) {
        int r = i >> 4, c4 = (i & 15) * 4;
        float4 v = *(const float4*)(QP + base + (size_t)(q0 + r) * D_MODEL + c4);
        float* dst = Qs + r * QS_STRIDE + c4;
        dst[0] = v.x * 0.125f; dst[1] = v.y * 0.125f;
        dst[2] = v.z * 0.125f; dst[3] = v.w * 0.125f;
    }

    float mrow[4], lrow[4];
    float4 o[4];
#pragma unroll
    for (int i = 0; i < 4; i++) {
        mrow[i] = -1e30f; lrow[i] = 0.0f;
        o[i] = make_float4(0.f, 0.f, 0.f, 0.f);
    }

    for (int k0 = 0; k0 < SEQ; k0 += 64) {
        __syncthreads();  // previous iteration's Ps/Vs reads complete
        // Load K & V tiles
        for (int i = tid; i < 64 * 16; i += 256) {
            int r = i >> 4, c4 = (i & 15) * 4;
            float4 kv = *(const float4*)(KP + base + (size_t)(k0 + r) * D_MODEL + c4);
            float* kd = Ks + r * QS_STRIDE + c4;
            kd[0] = kv.x; kd[1] = kv.y; kd[2] = kv.z; kd[3] = kv.w;
            float4 vv = *(const float4*)(VP + base + (size_t)(k0 + r) * D_MODEL + c4);
            *(float4*)(Vs + r * 64 + c4) = vv;
        }
        __syncthreads();

        // Scores: s[i][j] = Qs[ty*4+i] . Ks[tx*4+j]   (Q pre-scaled)
        float s[4][4];
#pragma unroll
        for (int i = 0; i < 4; i++)
#pragma unroll
            for (int j = 0; j < 4; j++) s[i][j] = 0.0f;

#pragma unroll
        for (int d4 = 0; d4 < 16; d4++) {
            float4 qa[4], kb[4];
#pragma unroll
            for (int i = 0; i < 4; i++)
                qa[i] = *(const float4*)(Qs + (ty * 4 + i) * QS_STRIDE + d4 * 4);
#pragma unroll
            for (int j = 0; j < 4; j++)
                kb[j] = *(const float4*)(Ks + (tx * 4 + j) * QS_STRIDE + d4 * 4);
#pragma unroll
            for (int i = 0; i < 4; i++)
#pragma unroll
                for (int j = 0; j < 4; j++)
                    s[i][j] += qa[i].x * kb[j].x + qa[i].y * kb[j].y +
                               qa[i].z * kb[j].z + qa[i].w * kb[j].w;
        }

        // Additive mask
#pragma unroll
        for (int i = 0; i < 4; i++) {
            float4 mk = *(const float4*)(mask + (size_t)(q0 + ty * 4 + i) * SEQ + k0 + tx * 4);
            s[i][0] += mk.x; s[i][1] += mk.y; s[i][2] += mk.z; s[i][3] += mk.w;
        }

        // Online softmax (reduce over the 16-lane tx group)
#pragma unroll
        for (int i = 0; i < 4; i++) {
            float mx = fmaxf(fmaxf(s[i][0], s[i][1]), fmaxf(s[i][2], s[i][3]));
#pragma unroll
            for (int off = 8; off >= 1; off >>= 1)
                mx = fmaxf(mx, __shfl_xor_sync(0xffffffffu, mx, off, 16));
            float mnew = fmaxf(mrow[i], mx);
            float corr = __expf(mrow[i] - mnew);
            float ps = 0.0f;
#pragma unroll
            for (int j = 0; j < 4; j++) {
                s[i][j] = __expf(s[i][j] - mnew);
                ps += s[i][j];
            }
#pragma unroll
            for (int off = 8; off >= 1; off >>= 1)
                ps += __shfl_xor_sync(0xffffffffu, ps, off, 16);
            lrow[i] = lrow[i] * corr + ps;
            mrow[i] = mnew;
            o[i].x *= corr; o[i].y *= corr; o[i].z *= corr; o[i].w *= corr;
        }

        // Stage P to smem
#pragma unroll
        for (int i = 0; i < 4; i++)
            *(float4*)(Ps + (ty * 4 + i) * 64 + tx * 4) =
                make_float4(s[i][0], s[i][1], s[i][2], s[i][3]);
        __syncthreads();

        // O += P @ V
#pragma unroll
        for (int c4 = 0; c4 < 16; c4++) {
            float4 p[4];
#pragma unroll
            for (int i = 0; i < 4; i++)
                p[i] = *(const float4*)(Ps + (ty * 4 + i) * 64 + c4 * 4);
#pragma unroll
            for (int cc = 0; cc < 4; cc++) {
                float4 vv = *(const float4*)(Vs + (c4 * 4 + cc) * 64 + tx * 4);
#pragma unroll
                for (int i = 0; i < 4; i++) {
                    float pw = ((const float*)&p[i])[cc];
                    o[i].x += pw * vv.x; o[i].y += pw * vv.y;
                    o[i].z += pw * vv.z; o[i].w += pw * vv.w;
                }
            }
        }
    }

    // Epilogue: normalize and store into (B, S, D) layout
#pragma unroll
    for (int i = 0; i < 4; i++) {
        float inv = 1.0f / lrow[i];
        float4 r = make_float4(o[i].x * inv, o[i].y * inv, o[i].z * inv, o[i].w * inv);
        *(float4*)(out + base + (size_t)(q0 + ty * 4 + i) * D_MODEL + tx * 4) = r;
    }
}

// ---------------------------------------------------------------------------

extern "C" void kernel_launch(void* const* d_in, const int* in_sizes, int n_in,
                              void* d_out, int out_size)
{
    const float* q    = (const float*)d_in[0];
    const float* k    = (const float*)d_in[1];
    const float* v    = (const float*)d_in[2];
    const float* mask = (const float*)d_in[3];
    const float* Wq   = (const float*)d_in[4];
    const float* bq   = (const float*)d_in[5];
    const float* Wk   = (const float*)d_in[6];
    const float* bk   = (const float*)d_in[7];
    const float* Wv   = (const float*)d_in[8];
    const float* bv   = (const float*)d_in[9];
    float* out = (float*)d_out;

    float *qp, *kp, *vp;
    cudaGetSymbolAddress((void**)&qp, g_qp);
    cudaGetSymbolAddress((void**)&kp, g_kp);
    cudaGetSymbolAddress((void**)&vp, g_vp);

    dim3 ggrid(1024 / 128, M_TOT / 128);  // (8, 32)
    proj_gemm<<<ggrid, 256>>>(q, Wq, bq, qp);
    proj_gemm<<<ggrid, 256>>>(k, Wk, bk, kp);
    proj_gemm<<<ggrid, 256>>>(v, Wv, bv, vp);

    const int smem = (2 * 64 * QS_STRIDE + 2 * 64 * 64) * (int)sizeof(float);  // 67584 B
    cudaFuncSetAttribute(attn_kernel, cudaFuncAttributeMaxDynamicSharedMemorySize, smem);
    attn_kernel<<<dim3(SEQ / 64, N_HEADS, BATCH), 256, smem>>>(qp, kp, vp, mask, out);
}

// round 2
// speedup vs baseline: 3.0343x; 3.0343x over previous
#include <cuda_runtime.h>

#define D_MODEL 1024
#define N_HEADS 16
#define HEAD    64
#define BATCH   2
#define SEQ     2048
#define M_TOT   (BATCH * SEQ)

// Scratch for projected Q/K/V — __device__ globals per harness rules.
__device__ float g_qp[M_TOT * D_MODEL];
__device__ float g_kp[M_TOT * D_MODEL];
__device__ float g_vp[M_TOT * D_MODEL];

// ---------------------------------------------------------------------------
// Helpers
// ---------------------------------------------------------------------------
__device__ __forceinline__ unsigned f2tf(float x) {
    unsigned r;
    asm("cvt.rna.tf32.f32 %0, %1;" : "=r"(r) : "f"(x));
    return r;
}

// D += A*B, m16n8k8 tf32, in-place accumulate
__device__ __forceinline__ void mma8(float* d, const unsigned* a, const unsigned* b) {
    asm volatile(
        "mma.sync.aligned.m16n8k8.row.col.f32.tf32.tf32.f32 "
        "{%0,%1,%2,%3}, {%4,%5,%6,%7}, {%8,%9}, {%0,%1,%2,%3};\n"
        : "+f"(d[0]), "+f"(d[1]), "+f"(d[2]), "+f"(d[3])
        : "r"(a[0]), "r"(a[1]), "r"(a[2]), "r"(a[3]), "r"(b[0]), "r"(b[1]));
}

// e^x using only FMA/ALU (no MUFU). Valid for x <= 0 (clamped at -80).
__device__ __forceinline__ float fast_exp(float x) {
    x = fmaxf(x, -80.0f);
    float y  = x * 1.44269504088896f;          // log2(e)
    float fy = y + 12582912.0f;                 // round-to-nearest-int (2^23+2^22)
    int   k  = __float_as_int(fy);              // low bits hold integer(y)
    float f  = y - (fy - 12582912.0f);          // f in [-0.5, 0.5]
    float p  = 1.33336e-3f;
    p = fmaf(p, f, 9.61812e-3f);
    p = fmaf(p, f, 5.55041e-2f);
    p = fmaf(p, f, 2.40226507e-1f);
    p = fmaf(p, f, 6.93147182e-1f);
    p = fmaf(p, f, 1.0f);
    return __int_as_float(__float_as_int(p) + (k << 23));
}

// ---------------------------------------------------------------------------
// Fused projection GEMM (tf32 tensor cores): Y = X @ W^T + b
// M=4096, N=1024, K=1024. Block tile 128x64, BK=32, 256 thr = 8 warps (4Mx2N),
// warp tile 32x32 = 2 m16 x 4 n8 fragments. blockIdx.z selects q/k/v.
// ---------------------------------------------------------------------------
#define PSTR 36   // smem row stride (words): 36 mod 32 = 4 -> conflict-free frags

__global__ __launch_bounds__(256) void proj_gemm_tc(
    const float* __restrict__ q, const float* __restrict__ k, const float* __restrict__ v,
    const float* __restrict__ Wq, const float* __restrict__ Wk, const float* __restrict__ Wv,
    const float* __restrict__ bq, const float* __restrict__ bk, const float* __restrict__ bv,
    float* __restrict__ yq, float* __restrict__ yk, float* __restrict__ yv)
{
    const int z = blockIdx.z;
    const float* X    = (z == 0) ? q  : (z == 1) ? k  : v;
    const float* W    = (z == 0) ? Wq : (z == 1) ? Wk : Wv;
    const float* bias = (z == 0) ? bq : (z == 1) ? bk : bv;
    float*       Y    = (z == 0) ? yq : (z == 1) ? yk : yv;

    __shared__ unsigned As[128][PSTR];
    __shared__ unsigned Bs[64][PSTR];

    const int tid  = threadIdx.x;
    const int lane = tid & 31, wid = tid >> 5;
    const int wm   = wid >> 1, wn = wid & 1;
    const int g    = lane >> 2, t = lane & 3;
    const int bm   = blockIdx.y * 128, bn = blockIdx.x * 64;

    const int arow = tid >> 1, acol = (tid & 1) * 16;
    const int brow = tid >> 2, bcol = (tid & 3) * 8;
    const float* Ap = X + (size_t)(bm + arow) * D_MODEL + acol;
    const float* Bp = W + (size_t)(bn + brow) * D_MODEL + bcol;

    float acc[2][4][4];
#pragma unroll
    for (int mi = 0; mi < 2; mi++)
#pragma unroll
        for (int ni = 0; ni < 4; ni++)
#pragma unroll
            for (int r = 0; r < 4; r++) acc[mi][ni][r] = 0.0f;

    float4 ra[4], rb[2];
#pragma unroll
    for (int i = 0; i < 4; i++) ra[i] = *(const float4*)(Ap + i * 4);
    rb[0] = *(const float4*)(Bp);
    rb[1] = *(const float4*)(Bp + 4);

    for (int k0 = 0; k0 < D_MODEL; k0 += 32) {
#pragma unroll
        for (int i = 0; i < 4; i++) {
            As[arow][acol + i * 4 + 0] = f2tf(ra[i].x);
            As[arow][acol + i * 4 + 1] = f2tf(ra[i].y);
            As[arow][acol + i * 4 + 2] = f2tf(ra[i].z);
            As[arow][acol + i * 4 + 3] = f2tf(ra[i].w);
        }
        Bs[brow][bcol + 0] = f2tf(rb[0].x); Bs[brow][bcol + 1] = f2tf(rb[0].y);
        Bs[brow][bcol + 2] = f2tf(rb[0].z); Bs[brow][bcol + 3] = f2tf(rb[0].w);
        Bs[brow][bcol + 4] = f2tf(rb[1].x); Bs[brow][bcol + 5] = f2tf(rb[1].y);
        Bs[brow][bcol + 6] = f2tf(rb[1].z); Bs[brow][bcol + 7] = f2tf(rb[1].w);
        __syncthreads();

        if (k0 + 32 < D_MODEL) {
#pragma unroll
            for (int i = 0; i < 4; i++) ra[i] = *(const float4*)(Ap + k0 + 32 + i * 4);
            rb[0] = *(const float4*)(Bp + k0 + 32);
            rb[1] = *(const float4*)(Bp + k0 + 36);
        }

#pragma unroll
        for (int kk = 0; kk < 4; kk++) {
            unsigned af[2][4], bf[4][2];
#pragma unroll
            for (int mi = 0; mi < 2; mi++) {
                int rb0 = wm * 32 + mi * 16;
                af[mi][0] = As[rb0 + g][kk * 8 + t];
                af[mi][1] = As[rb0 + 8 + g][kk * 8 + t];
                af[mi][2] = As[rb0 + g][kk * 8 + t + 4];
                af[mi][3] = As[rb0 + 8 + g][kk * 8 + t + 4];
            }
#pragma unroll
            for (int ni = 0; ni < 4; ni++) {
                int nb = wn * 32 + ni * 8;
                bf[ni][0] = Bs[nb + g][kk * 8 + t];
                bf[ni][1] = Bs[nb + g][kk * 8 + t + 4];
            }
#pragma unroll
            for (int mi = 0; mi < 2; mi++)
#pragma unroll
                for (int ni = 0; ni < 4; ni++)
                    mma8(acc[mi][ni], af[mi], bf[ni]);
        }
        __syncthreads();
    }

#pragma unroll
    for (int mi = 0; mi < 2; mi++) {
        int r0 = bm + wm * 32 + mi * 16 + g;
#pragma unroll
        for (int ni = 0; ni < 4; ni++) {
            int c = bn + wn * 32 + ni * 8 + 2 * t;
            float b0v = bias[c], b1v = bias[c + 1];
            float2 lo = make_float2(acc[mi][ni][0] + b0v, acc[mi][ni][1] + b1v);
            float2 hi = make_float2(acc[mi][ni][2] + b0v, acc[mi][ni][3] + b1v);
            *(float2*)(Y + (size_t)r0 * D_MODEL + c)       = lo;
            *(float2*)(Y + (size_t)(r0 + 8) * D_MODEL + c) = hi;
        }
    }
}

// ---------------------------------------------------------------------------
// Flash attention with tf32 tensor cores.
// Block: 128 threads (4 warps), 64 q-rows (warp w owns rows w*16..+15),
// key tiles of 64, head dim 64. Online softmax with FMA-only exp.
// P staged per-warp through smem (C-frag -> A-frag relayout).
// ---------------------------------------------------------------------------
#define ASTR 68   // smem row stride (words): 68 mod 32 = 4 -> conflict-free frags

__global__ __launch_bounds__(128) void attn_tc(
    const float* __restrict__ QP, const float* __restrict__ KP,
    const float* __restrict__ VP, const float* __restrict__ mask,
    float* __restrict__ out)
{
    extern __shared__ unsigned sm[];
    unsigned* Qs = sm;                 // [64][ASTR]
    unsigned* Ks = Qs + 64 * ASTR;
    unsigned* Vs = Ks + 64 * ASTR;
    unsigned* Ps = Vs + 64 * ASTR;

    const int tid  = threadIdx.x;
    const int lane = tid & 31, wid = tid >> 5;
    const int g    = lane >> 2, t = lane & 3;
    const int rw   = wid * 16;
    const int q0   = blockIdx.x * 64;
    const int h    = blockIdx.y;
    const int b    = blockIdx.z;
    const size_t base = (size_t)b * SEQ * D_MODEL + (size_t)h * HEAD;

    // Load Q tile once, pre-scaled by 1/sqrt(HEAD)=0.125
    for (int i = tid; i < 64 * 16; i += 128) {
        int r = i >> 4, c = (i & 15) * 4;
        float4 qv = *(const float4*)(QP + base + (size_t)(q0 + r) * D_MODEL + c);
        unsigned* d = Qs + r * ASTR + c;
        d[0] = f2tf(qv.x * 0.125f); d[1] = f2tf(qv.y * 0.125f);
        d[2] = f2tf(qv.z * 0.125f); d[3] = f2tf(qv.w * 0.125f);
    }

    float o[8][4];
#pragma unroll
    for (int nj = 0; nj < 8; nj++)
#pragma unroll
        for (int r = 0; r < 4; r++) o[nj][r] = 0.0f;
    float m0 = -1e30f, m1 = -1e30f, l0 = 0.0f, l1 = 0.0f;

    const int r0g = q0 + rw + g;      // global q row for c0/c1
    const int r1g = r0g + 8;          // global q row for c2/c3

    for (int k0 = 0; k0 < SEQ; k0 += 64) {
        __syncthreads();
        // Load K,V tiles (tf32)
        for (int i = tid; i < 64 * 16; i += 128) {
            int r = i >> 4, c = (i & 15) * 4;
            float4 kv = *(const float4*)(KP + base + (size_t)(k0 + r) * D_MODEL + c);
            unsigned* kd = Ks + r * ASTR + c;
            kd[0] = f2tf(kv.x); kd[1] = f2tf(kv.y); kd[2] = f2tf(kv.z); kd[3] = f2tf(kv.w);
            float4 vv = *(const float4*)(VP + base + (size_t)(k0 + r) * D_MODEL + c);
            unsigned* vd = Vs + r * ASTR + c;
            vd[0] = f2tf(vv.x); vd[1] = f2tf(vv.y); vd[2] = f2tf(vv.z); vd[3] = f2tf(vv.w);
        }
        __syncthreads();

        // S = Q @ K^T (per-warp 16x64)
        float s[8][4];
#pragma unroll
        for (int nj = 0; nj < 8; nj++)
#pragma unroll
            for (int r = 0; r < 4; r++) s[nj][r] = 0.0f;

#pragma unroll
        for (int kc = 0; kc < 8; kc++) {
            unsigned a[4];
            a[0] = Qs[(rw + g) * ASTR + kc * 8 + t];
            a[1] = Qs[(rw + 8 + g) * ASTR + kc * 8 + t];
            a[2] = Qs[(rw + g) * ASTR + kc * 8 + t + 4];
            a[3] = Qs[(rw + 8 + g) * ASTR + kc * 8 + t + 4];
#pragma unroll
            for (int nj = 0; nj < 8; nj++) {
                unsigned bf[2];
                bf[0] = Ks[(nj * 8 + g) * ASTR + kc * 8 + t];
                bf[1] = Ks[(nj * 8 + g) * ASTR + kc * 8 + t + 4];
                mma8(s[nj], a, bf);
            }
        }

        // Additive mask + row max
        float mx0 = -1e30f, mx1 = -1e30f;
#pragma unroll
        for (int nj = 0; nj < 8; nj++) {
            float2 mk0 = *(const float2*)(mask + (size_t)r0g * SEQ + k0 + nj * 8 + 2 * t);
            float2 mk1 = *(const float2*)(mask + (size_t)r1g * SEQ + k0 + nj * 8 + 2 * t);
            s[nj][0] += mk0.x; s[nj][1] += mk0.y;
            s[nj][2] += mk1.x; s[nj][3] += mk1.y;
            mx0 = fmaxf(mx0, fmaxf(s[nj][0], s[nj][1]));
            mx1 = fmaxf(mx1, fmaxf(s[nj][2], s[nj][3]));
        }
        mx0 = fmaxf(mx0, __shfl_xor_sync(0xffffffffu, mx0, 1));
        mx0 = fmaxf(mx0, __shfl_xor_sync(0xffffffffu, mx0, 2));
        mx1 = fmaxf(mx1, __shfl_xor_sync(0xffffffffu, mx1, 1));
        mx1 = fmaxf(mx1, __shfl_xor_sync(0xffffffffu, mx1, 2));

        float mn0 = fmaxf(m0, mx0), mn1 = fmaxf(m1, mx1);
        float c0 = fast_exp(m0 - mn0), c1 = fast_exp(m1 - mn1);
        float sum0 = 0.0f, sum1 = 0.0f;
#pragma unroll
        for (int nj = 0; nj < 8; nj++) {
            s[nj][0] = fast_exp(s[nj][0] - mn0);
            s[nj][1] = fast_exp(s[nj][1] - mn0);
            s[nj][2] = fast_exp(s[nj][2] - mn1);
            s[nj][3] = fast_exp(s[nj][3] - mn1);
            sum0 += s[nj][0] + s[nj][1];
            sum1 += s[nj][2] + s[nj][3];
        }
        sum0 += __shfl_xor_sync(0xffffffffu, sum0, 1);
        sum0 += __shfl_xor_sync(0xffffffffu, sum0, 2);
        sum1 += __shfl_xor_sync(0xffffffffu, sum1, 1);
        sum1 += __shfl_xor_sync(0xffffffffu, sum1, 2);

        l0 = l0 * c0 + sum0;  l1 = l1 * c1 + sum1;
        m0 = mn0;             m1 = mn1;
#pragma unroll
        for (int nj = 0; nj < 8; nj++) {
            o[nj][0] *= c0; o[nj][1] *= c0;
            o[nj][2] *= c1; o[nj][3] *= c1;
        }

        // Stage P (per-warp region only)
#pragma unroll
        for (int nj = 0; nj < 8; nj++) {
            Ps[(rw + g) * ASTR + nj * 8 + 2 * t]         = f2tf(s[nj][0]);
            Ps[(rw + g) * ASTR + nj * 8 + 2 * t + 1]     = f2tf(s[nj][1]);
            Ps[(rw + 8 + g) * ASTR + nj * 8 + 2 * t]     = f2tf(s[nj][2]);
            Ps[(rw + 8 + g) * ASTR + nj * 8 + 2 * t + 1] = f2tf(s[nj][3]);
        }
        __syncwarp();

        // O += P @ V
#pragma unroll
        for (int kc = 0; kc < 8; kc++) {
            unsigned a[4];
            a[0] = Ps[(rw + g) * ASTR + kc * 8 + t];
            a[1] = Ps[(rw + 8 + g) * ASTR + kc * 8 + t];
            a[2] = Ps[(rw + g) * ASTR + kc * 8 + t + 4];
            a[3] = Ps[(rw + 8 + g) * ASTR + kc * 8 + t + 4];
#pragma unroll
            for (int nj = 0; nj < 8; nj++) {
                unsigned bf[2];
                bf[0] = Vs[(kc * 8 + t) * ASTR + nj * 8 + g];
                bf[1] = Vs[(kc * 8 + t + 4) * ASTR + nj * 8 + g];
                mma8(o[nj], a, bf);
            }
        }
    }

    float inv0 = 1.0f / l0, inv1 = 1.0f / l1;
#pragma unroll
    for (int nj = 0; nj < 8; nj++) {
        float2 lo = make_float2(o[nj][0] * inv0, o[nj][1] * inv0);
        float2 hi = make_float2(o[nj][2] * inv1, o[nj][3] * inv1);
        *(float2*)(out + base + (size_t)r0g * D_MODEL + nj * 8 + 2 * t) = lo;
        *(float2*)(out + base + (size_t)r1g * D_MODEL + nj * 8 + 2 * t) = hi;
    }
}

// ---------------------------------------------------------------------------

extern "C" void kernel_launch(void* const* d_in, const int* in_sizes, int n_in,
                              void* d_out, int out_size)
{
    const float* q    = (const float*)d_in[0];
    const float* k    = (const float*)d_in[1];
    const float* v    = (const float*)d_in[2];
    const float* mask = (const float*)d_in[3];
    const float* Wq   = (const float*)d_in[4];
    const float* bq   = (const float*)d_in[5];
    const float* Wk   = (const float*)d_in[6];
    const float* bk   = (const float*)d_in[7];
    const float* Wv   = (const float*)d_in[8];
    const float* bv   = (const float*)d_in[9];
    float* out = (float*)d_out;

    float *qp, *kp, *vp;
    cudaGetSymbolAddress((void**)&qp, g_qp);
    cudaGetSymbolAddress((void**)&kp, g_kp);
    cudaGetSymbolAddress((void**)&vp, g_vp);

    dim3 pgrid(D_MODEL / 64, M_TOT / 128, 3);   // (16, 32, 3)
    proj_gemm_tc<<<pgrid, 256>>>(q, k, v, Wq, Wk, Wv, bq, bk, bv, qp, kp, vp);

    const int smem = 4 * 64 * ASTR * (int)sizeof(unsigned);  // 69632 B
    cudaFuncSetAttribute(attn_tc, cudaFuncAttributeMaxDynamicSharedMemorySize, smem);
    attn_tc<<<dim3(SEQ / 64, N_HEADS, BATCH), 128, smem>>>(qp, kp, vp, mask, out);
}